// round 4
// baseline (speedup 1.0000x reference)
#include <cuda_runtime.h>

#define TT     2190
#define NWARM  365
#define NMAIN  1825
#define NG     10000
#define NH     5000                     // cells per chain-slot (2 cells/thread)
#define KER    15
#define PF     5
#define G3     (NG * 3)
#define CH     25                       // 1825 = 73 * 25

// scratch (device globals: the sanctioned no-alloc workaround)
__device__ float g_q[NMAIN * NG];       // raw simulated discharge, 73 MB
__device__ float g_uh[KER * NG];        // per-cell unit hydrograph

// ---------------------------------------------------------------------------
// per-cell parameter/state bundle
// ---------------------------------------------------------------------------
struct Cell {
    float beta, inv_fc, fc, inv_lpfc, pperc, uzl, tt, cfmax, mcf, cfr, cwh,
          k0, omk1, omk2;
    float sp, mw, sm, suz, slz;
};

__device__ __forceinline__ void cell_init(Cell& c, const float* __restrict__ par, int g)
{
    float raw[14];
    #pragma unroll
    for (int i = 0; i < 14; ++i) raw[i] = par[g * 14 + i];
    c.beta    = 1.0f   + raw[0]  * 5.0f;
    c.fc      = 50.0f  + raw[1]  * 950.0f;
    c.k0      = 0.05f  + raw[2]  * 0.85f;
    float k1  = 0.01f  + raw[3]  * 0.49f;
    float k2  = 0.001f + raw[4]  * 0.199f;
    float lp  = 0.2f   + raw[5]  * 0.8f;
    c.pperc   =          raw[6]  * 10.0f;
    c.uzl     =          raw[7]  * 100.0f;
    c.tt      = -2.5f  + raw[8]  * 5.0f;
    c.cfmax   = 0.5f   + raw[9]  * 9.5f;
    c.cfr     =          raw[10] * 0.1f;
    c.cwh     =          raw[11] * 0.2f;
    c.mcf     = -c.cfmax * c.tt;
    c.inv_fc  = 1.0f / c.fc;
    c.inv_lpfc= 1.0f / (lp * c.fc);
    c.omk1    = 1.0f - k1;
    c.omk2    = 1.0f - k2;
    c.sp = 0.001f; c.mw = 0.001f; c.sm = 0.001f; c.suz = 0.001f; c.slz = 0.001f;
}

// one HBV timestep; chain-minimized, clamp-free where invariants allow
__device__ __forceinline__ float step(Cell& c, float precip, float pet, float tm)
{
    float rain = (tm >= c.tt) ? precip : 0.0f;
    float snow = precip - rain;
    float d    = fmaf(c.cfmax, tm, c.mcf);               // cfmax*(tm-tt)
    float sp1  = c.sp + snow;
    float melt = fminf(fmaxf(d, 0.0f), sp1);
    float mw1  = c.mw + melt;
    float cfrd = c.cfr * d;
    float refr = fminf(fmaxf(-cfrd, 0.0f), mw1);         // cfr*cfmax*(tt-tm)
    float mw2  = mw1 - refr;
    float sp2  = sp1 - melt + refr;
    float ts   = fmaxf(fmaf(-c.cwh, sp2, mw2), 0.0f);
    c.mw = mw2 - ts;
    c.sp = sp2;
    // sm <= fc and beta >= 1  =>  sw <= 1 structurally; no clamp needed
    float sw   = __powf(c.sm * c.inv_fc, c.beta);
    float rts  = rain + ts;
    float srts = c.sm + rts;                             // off sw-chain
    float sm1  = fmaf(-rts, sw, srts);                   // sm + rts*(1-sw)
    float rech = rts * sw;
    float sm2  = fminf(sm1, c.fc);
    float exc  = sm1 - sm2;                              // max(sm1-fc,0)
    float pil  = pet * c.inv_lpfc;                       // off sm-chain
    float t2   = fminf(sm2 * pil, pet);                  // pet*clip(ef,0,1)
    c.sm       = fmaxf(sm2 - t2, 1e-5f);                 // sm - min(sm, pet*ef)
    float suz2 = c.suz + rech + exc;
    float perc = fminf(suz2, c.pperc);
    float suz3 = suz2 - perc;
    float q0   = c.k0 * fmaxf(suz3 - c.uzl, 0.0f);
    float suzn = (suz3 - q0) * c.omk1;                   // q0+q1 = suz3 - suzn
    float slz1 = c.slz + perc;
    float slzn = slz1 * c.omk2;                          // q2 = slz1 - slzn
    c.suz = suzn;
    c.slz = slzn;
    return (suz3 - suzn) + (slz1 - slzn);
}

// ---------------------------------------------------------------------------
// K0: gamma unit hydrograph per cell (gammaln & a*log(theta) cancel in norm)
// ---------------------------------------------------------------------------
__global__ void __launch_bounds__(256)
uh_kernel(const float* __restrict__ par)
{
    int g = blockIdx.x * blockDim.x + threadIdx.x;
    if (g >= NG) return;
    float a   = fmaf(par[g * 14 + 12], 2.9f, 0.1f);
    float th  = fmaf(par[g * 14 + 13], 6.5f, 0.5f);
    float am1 = a - 1.0f;
    float ith = 1.0f / th;

    float w[KER], s = 0.0f;
    #pragma unroll
    for (int k = 0; k < KER; ++k) {
        float tk = (float)k + 0.5f;
        w[k] = __expf(fmaf(am1, __logf(tk), -tk * ith));
        s += w[k];
    }
    float inv = 1.0f / s;
    #pragma unroll
    for (int k = 0; k < KER; ++k) g_uh[k * NG + g] = w[k] * inv;
}

// ---------------------------------------------------------------------------
// K1: sequential HBV scan, TWO independent cells per thread. The second chain
// fills the in-order dependency bubbles of the first (MUFU/fma latency).
// ---------------------------------------------------------------------------
__global__ void __launch_bounds__(64)
hbv_scan_kernel(const float* __restrict__ x, const float* __restrict__ par)
{
    int i = blockIdx.x * blockDim.x + threadIdx.x;
    if (i >= NH) return;
    int gA = i, gB = i + NH;

    Cell cA, cB;
    cell_init(cA, par, gA);
    cell_init(cB, par, gB);

    const float* __restrict__ xA = x + gA * 3;
    const float* __restrict__ xB = x + gB * 3;

    // software prefetch ring, distance PF steps, both cells
    float pA[PF], eA[PF], tA[PF], pB[PF], eB[PF], tB[PF];
    #pragma unroll
    for (int k = 0; k < PF; ++k) {
        pA[k] = xA[k * G3 + 0]; eA[k] = xA[k * G3 + 1]; tA[k] = xA[k * G3 + 2];
        pB[k] = xB[k * G3 + 0]; eB[k] = xB[k * G3 + 1]; tB[k] = xB[k * G3 + 2];
    }
    int off = PF * G3;

    // ---- warmup: 365 steps (73 x 5), always prefetch (max load step 369) ----
    #pragma unroll 1
    for (int it = 0; it < NWARM / PF; ++it) {
        #pragma unroll
        for (int u = 0; u < PF; ++u) {
            float pav = pA[u], eav = eA[u], tav = tA[u];
            float pbv = pB[u], ebv = eB[u], tbv = tB[u];
            pA[u] = xA[off + 0]; eA[u] = xA[off + 1]; tA[u] = xA[off + 2];
            pB[u] = xB[off + 0]; eB[u] = xB[off + 1]; tB[u] = xB[off + 2];
            off += G3;
            (void)step(cA, pav, eav, tav);
            (void)step(cB, pbv, ebv, tbv);
        }
    }

    // ---- main A: 1820 steps (364 x 5) with prefetch (last load = step 2189) ----
    float* __restrict__ qpA = g_q + gA;
    float* __restrict__ qpB = g_q + gB;
    #pragma unroll 1
    for (int it = 0; it < (NMAIN - PF) / PF; ++it) {
        #pragma unroll
        for (int u = 0; u < PF; ++u) {
            float pav = pA[u], eav = eA[u], tav = tA[u];
            float pbv = pB[u], ebv = eB[u], tbv = tB[u];
            pA[u] = xA[off + 0]; eA[u] = xA[off + 1]; tA[u] = xA[off + 2];
            pB[u] = xB[off + 0]; eB[u] = xB[off + 1]; tB[u] = xB[off + 2];
            off += G3;
            *qpA = step(cA, pav, eav, tav);
            *qpB = step(cB, pbv, ebv, tbv);
            qpA += NG; qpB += NG;
        }
    }

    // ---- main B: final 5 steps, drain the ring ----
    #pragma unroll
    for (int u = 0; u < PF; ++u) {
        *qpA = step(cA, pA[u], eA[u], tA[u]);
        *qpB = step(cB, pB[u], eB[u], tB[u]);
        qpA += NG; qpB += NG;
    }
}

// ---------------------------------------------------------------------------
// K2: 15-tap causal convolution, fully parallel. Thread = (cell, 25-step chunk).
// ---------------------------------------------------------------------------
__global__ void __launch_bounds__(256)
conv_kernel(float* __restrict__ out)
{
    int g = blockIdx.x * blockDim.x + threadIdx.x;
    if (g >= NG) return;
    int t0 = blockIdx.y * CH;

    float uh[KER];
    #pragma unroll
    for (int k = 0; k < KER; ++k) uh[k] = g_uh[k * NG + g];

    float w[KER - 1];
    #pragma unroll
    for (int j = 0; j < KER - 1; ++j) {
        int t = t0 - 1 - j;
        w[j] = (t >= 0) ? g_q[t * NG + g] : 0.0f;
    }

    #pragma unroll
    for (int s = 0; s < CH; ++s) {
        float qn = g_q[(t0 + s) * NG + g];
        float o  = uh[0] * qn;
        #pragma unroll
        for (int j = 0; j < KER - 1; ++j)
            o = fmaf(uh[j + 1], w[j], o);
        out[(t0 + s) * NG + g] = o;
        #pragma unroll
        for (int j = KER - 2; j > 0; --j) w[j] = w[j - 1];
        w[0] = qn;
    }
}

// ---------------------------------------------------------------------------
extern "C" void kernel_launch(void* const* d_in, const int* in_sizes, int n_in,
                              void* d_out, int out_size)
{
    const float* x   = (const float*)d_in[0];   // (2190, 10000, 3) f32
    const float* par = (const float*)d_in[1];   // (10000, 14) f32
    float*       out = (float*)d_out;           // (1825, 10000, 1) f32

    uh_kernel<<<(NG + 255) / 256, 256>>>(par);
    hbv_scan_kernel<<<(NH + 63) / 64, 64>>>(x, par);
    conv_kernel<<<dim3((NG + 255) / 256, NMAIN / CH), 256>>>(out);
}

// round 5
// speedup vs baseline: 1.8084x; 1.8084x over previous
#include <cuda_runtime.h>
#include <cstdint>

#define TT     2190
#define NWARM  365
#define NMAIN  1825
#define NG     10000
#define KER    15
#define CH     25
#define BLK    128
#define DPF    12                       // prefetch depth in steps
#define RING   16                       // smem ring slots (power of 2 > DPF)
#define ROWB   (NG * 3 * 4)             // bytes per time row
#define SLOTF  (BLK * 3)                // floats per ring slot

// scratch (device globals: the sanctioned no-alloc workaround)
__device__ float g_q[NMAIN * NG];       // raw simulated discharge, 73 MB
__device__ float g_uh[KER * NG];        // per-cell unit hydrograph

// ---------------------------------------------------------------------------
struct Cell {
    float beta, inv_fc, fc, inv_lpfc, pperc, uzl, tt, cfmax, mcf, cfr, cwh,
          k0, omk1, omk2;
    float sp, mw, sm, suz, slz;
};

__device__ __forceinline__ void cell_init(Cell& c, const float* __restrict__ par, int g)
{
    float raw[14];
    #pragma unroll
    for (int i = 0; i < 14; ++i) raw[i] = par[g * 14 + i];
    c.beta    = 1.0f   + raw[0]  * 5.0f;
    c.fc      = 50.0f  + raw[1]  * 950.0f;
    c.k0      = 0.05f  + raw[2]  * 0.85f;
    float k1  = 0.01f  + raw[3]  * 0.49f;
    float k2  = 0.001f + raw[4]  * 0.199f;
    float lp  = 0.2f   + raw[5]  * 0.8f;
    c.pperc   =          raw[6]  * 10.0f;
    c.uzl     =          raw[7]  * 100.0f;
    c.tt      = -2.5f  + raw[8]  * 5.0f;
    c.cfmax   = 0.5f   + raw[9]  * 9.5f;
    c.cfr     =          raw[10] * 0.1f;
    c.cwh     =          raw[11] * 0.2f;
    c.mcf     = -c.cfmax * c.tt;
    c.inv_fc  = 1.0f / c.fc;
    c.inv_lpfc= 1.0f / (lp * c.fc);
    c.omk1    = 1.0f - k1;
    c.omk2    = 1.0f - k2;
    c.sp = 0.001f; c.mw = 0.001f; c.sm = 0.001f; c.suz = 0.001f; c.slz = 0.001f;
}

// one HBV timestep; chain-minimized, clamp-free where invariants allow
__device__ __forceinline__ float step(Cell& c, float precip, float pet, float tm)
{
    float rain = (tm >= c.tt) ? precip : 0.0f;
    float snow = precip - rain;
    float d    = fmaf(c.cfmax, tm, c.mcf);               // cfmax*(tm-tt)
    float sp1  = c.sp + snow;
    float melt = fminf(fmaxf(d, 0.0f), sp1);
    float mw1  = c.mw + melt;
    float cfrd = c.cfr * d;
    float refr = fminf(fmaxf(-cfrd, 0.0f), mw1);         // cfr*cfmax*(tt-tm)
    float mw2  = mw1 - refr;
    float sp2  = sp1 - melt + refr;
    float ts   = fmaxf(fmaf(-c.cwh, sp2, mw2), 0.0f);
    c.mw = mw2 - ts;
    c.sp = sp2;
    // sm <= fc and beta >= 1  =>  sw <= 1 structurally; no clamp needed
    float sw   = __powf(c.sm * c.inv_fc, c.beta);
    float rts  = rain + ts;
    float srts = c.sm + rts;                             // off sw-chain
    float sm1  = fmaf(-rts, sw, srts);                   // sm + rts*(1-sw)
    float rech = rts * sw;
    float sm2  = fminf(sm1, c.fc);
    float exc  = sm1 - sm2;                              // max(sm1-fc,0)
    float pil  = pet * c.inv_lpfc;                       // off sm-chain
    float t2   = fminf(sm2 * pil, pet);                  // pet*clip(ef,0,1)
    c.sm       = fmaxf(sm2 - t2, 1e-5f);                 // sm - min(sm, pet*ef)
    float suz2 = c.suz + rech + exc;
    float perc = fminf(suz2, c.pperc);
    float suz3 = suz2 - perc;
    float q0   = c.k0 * fmaxf(suz3 - c.uzl, 0.0f);
    float suzn = (suz3 - q0) * c.omk1;                   // q0+q1 = suz3 - suzn
    float slz1 = c.slz + perc;
    float slzn = slz1 * c.omk2;                          // q2 = slz1 - slzn
    c.suz = suzn;
    c.slz = slzn;
    return (suz3 - suzn) + (slz1 - slzn);
}

// ---------------------------------------------------------------------------
__device__ __forceinline__ void cp4(uint32_t dst, const char* src)
{
    asm volatile("cp.async.ca.shared.global [%0], [%1], 4;"
                 :: "r"(dst), "l"(src));
}
__device__ __forceinline__ void cp_commit()
{
    asm volatile("cp.async.commit_group;");
}
__device__ __forceinline__ void cp_wait_keep11()
{
    asm volatile("cp.async.wait_group 11;");   // DPF-1
}

// ---------------------------------------------------------------------------
// K0: gamma unit hydrograph per cell
// ---------------------------------------------------------------------------
__global__ void __launch_bounds__(256)
uh_kernel(const float* __restrict__ par)
{
    int g = blockIdx.x * blockDim.x + threadIdx.x;
    if (g >= NG) return;
    float a   = fmaf(par[g * 14 + 12], 2.9f, 0.1f);
    float th  = fmaf(par[g * 14 + 13], 6.5f, 0.5f);
    float am1 = a - 1.0f;
    float ith = 1.0f / th;

    float w[KER], s = 0.0f;
    #pragma unroll
    for (int k = 0; k < KER; ++k) {
        float tk = (float)k + 0.5f;
        w[k] = __expf(fmaf(am1, __logf(tk), -tk * ith));
        s += w[k];
    }
    float inv = 1.0f / s;
    #pragma unroll
    for (int k = 0; k < KER; ++k) g_uh[k * NG + g] = w[k] * inv;
}

// ---------------------------------------------------------------------------
// K1: sequential HBV scan, 1 cell/thread, cp.async smem prefetch ring.
// Each thread copies only its OWN 12B/step -> no __syncthreads anywhere.
// wait_group gives exact 12-step-deep FIFO: no scoreboard-slot aliasing.
// ---------------------------------------------------------------------------
__global__ void __launch_bounds__(128, 1)
hbv_scan_kernel(const float* __restrict__ x, const float* __restrict__ par)
{
    __shared__ float ring[RING * SLOTF];

    int tid = threadIdx.x;
    int g   = blockIdx.x * BLK + tid;
    bool active = (g < NG);
    int gc  = active ? g : (NG - 1);    // clamp for param read

    Cell c;
    cell_init(c, par, gc);

    // smem u32 address of this thread's 12B within slot 0
    uint32_t sb = (uint32_t)__cvta_generic_to_shared(ring) + (uint32_t)tid * 12u;
    const float* __restrict__ myr = ring + tid * 3;

    // per-thread global source column, advancing one time-row per copy
    const char* src = (const char*)x + (size_t)g * 12u;

    // ---- prologue: prefetch steps 0..DPF-1 ----
    #pragma unroll
    for (int s = 0; s < DPF; ++s) {
        uint32_t dst = sb + (uint32_t)s * (SLOTF * 4);
        if (active) { cp4(dst, src); cp4(dst + 4, src + 4); cp4(dst + 8, src + 8); }
        cp_commit();
        src += ROWB;
    }

    int rd = 0;           // ring slot of current step
    int wr = DPF;         // ring slot being filled

    // ---- warmup: 365 steps, copies unconditional (last target step 376) ----
    #pragma unroll 1
    for (int it = 0; it < NWARM / 5; ++it) {
        #pragma unroll
        for (int u = 0; u < 5; ++u) {
            cp_wait_keep11();                    // step-rd data resident
            int rb = rd * SLOTF;
            float p  = myr[rb + 0];
            float e  = myr[rb + 1];
            float tm = myr[rb + 2];
            uint32_t dst = sb + (uint32_t)wr * (SLOTF * 4);
            if (active) { cp4(dst, src); cp4(dst + 4, src + 4); cp4(dst + 8, src + 8); }
            cp_commit();
            src += ROWB;
            rd = (rd + 1) & (RING - 1);
            wr = (wr + 1) & (RING - 1);
            (void)step(c, p, e, tm);
        }
    }

    // ---- main: 1825 steps, copies guarded near the end of the series ----
    float* __restrict__ qp = g_q + g;
    int ncpy = NWARM + DPF;                      // next copy target step
    #pragma unroll 1
    for (int it = 0; it < NMAIN / 5; ++it) {
        #pragma unroll
        for (int u = 0; u < 5; ++u) {
            cp_wait_keep11();
            int rb = rd * SLOTF;
            float p  = myr[rb + 0];
            float e  = myr[rb + 1];
            float tm = myr[rb + 2];
            uint32_t dst = sb + (uint32_t)wr * (SLOTF * 4);
            if (active && ncpy < TT) { cp4(dst, src); cp4(dst + 4, src + 4); cp4(dst + 8, src + 8); }
            cp_commit();                          // empty groups keep FIFO depth
            src += ROWB;
            ncpy++;
            rd = (rd + 1) & (RING - 1);
            wr = (wr + 1) & (RING - 1);
            float q = step(c, p, e, tm);
            if (active) *qp = q;
            qp += NG;
        }
    }
    asm volatile("cp.async.wait_group 0;");      // drain before exit
}

// ---------------------------------------------------------------------------
// K2: 15-tap causal convolution, fully parallel. Thread = (cell, 25-step chunk).
// ---------------------------------------------------------------------------
__global__ void __launch_bounds__(256)
conv_kernel(float* __restrict__ out)
{
    int g = blockIdx.x * blockDim.x + threadIdx.x;
    if (g >= NG) return;
    int t0 = blockIdx.y * CH;

    float uh[KER];
    #pragma unroll
    for (int k = 0; k < KER; ++k) uh[k] = g_uh[k * NG + g];

    float w[KER - 1];
    #pragma unroll
    for (int j = 0; j < KER - 1; ++j) {
        int t = t0 - 1 - j;
        w[j] = (t >= 0) ? g_q[t * NG + g] : 0.0f;
    }

    #pragma unroll
    for (int s = 0; s < CH; ++s) {
        float qn = g_q[(t0 + s) * NG + g];
        float o  = uh[0] * qn;
        #pragma unroll
        for (int j = 0; j < KER - 1; ++j)
            o = fmaf(uh[j + 1], w[j], o);
        out[(t0 + s) * NG + g] = o;
        #pragma unroll
        for (int j = KER - 2; j > 0; --j) w[j] = w[j - 1];
        w[0] = qn;
    }
}

// ---------------------------------------------------------------------------
extern "C" void kernel_launch(void* const* d_in, const int* in_sizes, int n_in,
                              void* d_out, int out_size)
{
    const float* x   = (const float*)d_in[0];   // (2190, 10000, 3) f32
    const float* par = (const float*)d_in[1];   // (10000, 14) f32
    float*       out = (float*)d_out;           // (1825, 10000, 1) f32

    uh_kernel<<<(NG + 255) / 256, 256>>>(par);
    hbv_scan_kernel<<<(NG + BLK - 1) / BLK, BLK>>>(x, par);
    conv_kernel<<<dim3((NG + 255) / 256, NMAIN / CH), 256>>>(out);
}